// round 9
// baseline (speedup 1.0000x reference)
#include <cuda_runtime.h>
#include <cuda_fp16.h>
#include <cstdint>

#define NN   50000
#define EE   1600000
#define INC  128
#define OUTC 64
#define BKT  96          // fixed bucket capacity per node (mean deg 32, +11 sigma)

// Scratch (allocation-free contract: __device__ globals)
__device__ int   g_cnt[NN];                         // degree / fill cursor
__device__ __align__(16) __half g_feat[(size_t)NN * OUTC];  // fp16 features
__device__ int   g_src[(size_t)NN * BKT];           // bucketed source ids (19.2 MB)
__device__ int   g_is64;

// ---------------- zero + dtype detect (fused) ----------------
__global__ void zero_k(const int* __restrict__ ei32, int n) {
    int i = blockIdx.x * blockDim.x + threadIdx.x;
    if (i < n) g_cnt[i] = 0;
    if (blockIdx.x == 0) {
        // dtype probe: odd 32-bit words are zero iff int64 (high halves)
        __shared__ int zeros;
        if (threadIdx.x == 0) zeros = 0;
        __syncthreads();
        int z = (ei32[2 * threadIdx.x + 1] == 0) ? 1 : 0;
        atomicAdd(&zeros, z);
        __syncthreads();
        if (threadIdx.x == 0) g_is64 = (zeros > 128) ? 1 : 0;
    }
}

__device__ __forceinline__ int load_idx(const int* ei32, size_t pos) {
    if (g_is64) return (int)((const long long*)ei32)[pos];
    return ei32[pos];
}

// ---------------- bucketed fill: one pass, 8 edges/thread (MLP=8) ---------
__global__ void fill_k(const int* __restrict__ ei32, int E) {
    int e0 = (blockIdx.x * blockDim.x + threadIdx.x) * 8;
    if (e0 >= E) return;
    if (e0 + 8 <= E) {
        int r[8], c[8];
        if (g_is64) {
            const longlong2* pr = (const longlong2*)ei32;
            const longlong2* pc = (const longlong2*)((const long long*)ei32 + E);
#pragma unroll
            for (int q = 0; q < 4; q++) {
                longlong2 rv = pr[(e0 >> 1) + q];
                longlong2 cv = pc[(e0 >> 1) + q];
                r[q * 2] = (int)rv.x; r[q * 2 + 1] = (int)rv.y;
                c[q * 2] = (int)cv.x; c[q * 2 + 1] = (int)cv.y;
            }
        } else {
#pragma unroll
            for (int q = 0; q < 2; q++) {
                int4 rv = ((const int4*)ei32)[(e0 >> 2) + q];
                int4 cv = ((const int4*)(ei32 + E))[(e0 >> 2) + q];
                r[q * 4 + 0] = rv.x; r[q * 4 + 1] = rv.y;
                r[q * 4 + 2] = rv.z; r[q * 4 + 3] = rv.w;
                c[q * 4 + 0] = cv.x; c[q * 4 + 1] = cv.y;
                c[q * 4 + 2] = cv.z; c[q * 4 + 3] = cv.w;
            }
        }
        int p[8];
#pragma unroll
        for (int j = 0; j < 8; j++) p[j] = atomicAdd(&g_cnt[c[j]], 1);
#pragma unroll
        for (int j = 0; j < 8; j++) g_src[(size_t)c[j] * BKT + p[j]] = r[j];
    } else {
        for (int e = e0; e < E; e++) {
            int rr = load_idx(ei32, (size_t)e);
            int cc = load_idx(ei32, (size_t)E + e);
            int pp = atomicAdd(&g_cnt[cc], 1);
            g_src[(size_t)cc * BKT + pp] = rr;
        }
    }
}

// ---------------- fused linear + pre-scale: g_feat = fp16((x@W)*dinv) ------
// Packed f32x2 FMA (Blackwell FFMA2): 2 outputs per instruction.
__global__ __launch_bounds__(128) void gemm_k(
    const float* __restrict__ x, const float* __restrict__ W, int n)
{
    __shared__ __align__(16) float Ws[INC * OUTC];   // [k][o], 32 KB
    const float4* W4 = (const float4*)W;
    float4* Ws4 = (float4*)Ws;
    for (int i = threadIdx.x; i < INC * (OUTC / 4); i += 128) Ws4[i] = W4[i];
    __syncthreads();

    int row = blockIdx.x * 128 + threadIdx.x;
    if (row >= n) return;

    unsigned long long acc2[OUTC / 2];   // packed f32x2 accumulators
#pragma unroll
    for (int o = 0; o < OUTC / 2; o++) acc2[o] = 0ULL;

    const float4* xr = (const float4*)(x + (size_t)row * INC);
    const ulonglong2* WsP = (const ulonglong2*)Ws;  // [k][o4] as 2 packed pairs
#pragma unroll 4
    for (int k4 = 0; k4 < INC / 4; k4++) {
        float4 xq = __ldg(xr + k4);
        float xv[4] = {xq.x, xq.y, xq.z, xq.w};
#pragma unroll
        for (int j = 0; j < 4; j++) {
            int k = k4 * 4 + j;
            unsigned long long xx;
            asm("mov.b64 %0, {%1, %1};" : "=l"(xx) : "r"(__float_as_uint(xv[j])));
#pragma unroll
            for (int o4 = 0; o4 < OUTC / 4; o4++) {
                ulonglong2 wv = WsP[k * (OUTC / 4) + o4];
                asm("fma.rn.f32x2 %0, %1, %2, %0;" : "+l"(acc2[o4 * 2 + 0]) : "l"(xx), "l"(wv.x));
                asm("fma.rn.f32x2 %0, %1, %2, %0;" : "+l"(acc2[o4 * 2 + 1]) : "l"(xx), "l"(wv.y));
            }
        }
    }

    float s = rsqrtf((float)(g_cnt[row] + 1));   // +1 self-loop
    __half2* gp = (__half2*)(g_feat + (size_t)row * OUTC);  // 32 half2
#pragma unroll
    for (int o2 = 0; o2 < OUTC / 2; o2++) {
        unsigned int lo, hi;
        asm("mov.b64 {%0, %1}, %2;" : "=r"(lo), "=r"(hi) : "l"(acc2[o2]));
        gp[o2] = __floats2half2_rn(__uint_as_float(lo) * s, __uint_as_float(hi) * s);
    }
}

// ---------------- warp-per-node gather + epilogue ----------------
// Warp loads 32 src indices coalesced from its bucket, shuffles each out; all
// 32 lanes load a half2 slice per edge (128B/edge = one line).
// fp16 accumulation into 8 rotating half2 accumulators (4 instrs/edge);
// combined + scaled + biased in fp32.
__global__ __launch_bounds__(256) void gather_k(
    const float* __restrict__ b, float* __restrict__ out, int n)
{
    int warp = (blockIdx.x * blockDim.x + threadIdx.x) >> 5;
    if (warp >= n) return;
    int lane = threadIdx.x & 31;

    const __half2* gf = (const __half2*)g_feat;   // 32 half2 per node
    float2 self = __half22float2(gf[(size_t)warp * 32 + lane]);  // self-loop

    __half2 acch[8];
#pragma unroll
    for (int i = 0; i < 8; i++) acch[i] = __float2half2_rn(0.f);

    int cnt = g_cnt[warp];
    const int* bucket = g_src + (size_t)warp * BKT;
    for (int base = 0; base < cnt; base += 32) {
        int rem = cnt - base;
        int idx = (lane < rem) ? bucket[base + lane] : 0;
        if (rem >= 32) {
#pragma unroll
            for (int k = 0; k < 32; k++) {
                int r = __shfl_sync(0xffffffffu, idx, k);
                acch[k & 7] = __hadd2(acch[k & 7],
                                      __ldg(gf + (size_t)r * 32 + lane));
            }
        } else {
            for (int k = 0; k < rem; k++) {
                int r = __shfl_sync(0xffffffffu, idx, k);
                acch[k & 7] = __hadd2(acch[k & 7],
                                      __ldg(gf + (size_t)r * 32 + lane));
            }
        }
    }

    float2 acc = self;
#pragma unroll
    for (int i = 0; i < 8; i++) {
        float2 v = __half22float2(acch[i]);
        acc.x += v.x; acc.y += v.y;
    }

    float  s  = rsqrtf((float)(cnt + 1));
    float2 bq = __ldg((const float2*)b + lane);
    float2 o;
    o.x = acc.x * s + bq.x;
    o.y = acc.y * s + bq.y;
    ((float2*)out)[(size_t)warp * 32 + lane] = o;
}

extern "C" void kernel_launch(void* const* d_in, const int* in_sizes, int n_in,
                              void* d_out, int out_size)
{
    const float* x    = (const float*)d_in[0];
    const int*   ei32 = (const int*)d_in[1];
    const float* W    = (const float*)d_in[2];
    const float* b    = (const float*)d_in[3];
    float* out = (float*)d_out;

    int n = in_sizes[0] / INC;   // 50000
    int E = in_sizes[1] / 2;     // 1600000

    zero_k<<<(n + 255) / 256, 256>>>(ei32, n);          // + dtype detect
    fill_k<<<(E / 8 + 255) / 256, 256>>>(ei32, E);      // bucketed, 8 edges/thread
    gemm_k<<<(n + 127) / 128, 128>>>(x, W, n);          // f32x2 FMA, dinv from cnt
    gather_k<<<(n * 32 + 255) / 256, 256>>>(b, out, n); // fp16 accumulation
}

// round 10
// speedup vs baseline: 1.1106x; 1.1106x over previous
#include <cuda_runtime.h>
#include <cstdint>

#define NN   50000
#define EE   1600000
#define INC  128
#define OUTC 64
#define BKT  96          // fixed bucket capacity per node (mean deg 32, +11 sigma)

// Scratch (allocation-free contract: __device__ globals)
__device__ int   g_cnt[NN];                         // degree / fill cursor
__device__ __align__(16) float g_feat[(size_t)NN * OUTC];  // fp32 features
__device__ int   g_src[(size_t)NN * BKT];           // bucketed source ids (19.2 MB)
__device__ int   g_is64;

// ---------------- zero + dtype detect (fused) ----------------
__global__ void zero_k(const int* __restrict__ ei32, int n) {
    int i = blockIdx.x * blockDim.x + threadIdx.x;
    if (i < n) g_cnt[i] = 0;
    if (blockIdx.x == 0) {
        // dtype probe: odd 32-bit words are zero iff int64 (high halves)
        __shared__ int zeros;
        if (threadIdx.x == 0) zeros = 0;
        __syncthreads();
        int z = (ei32[2 * threadIdx.x + 1] == 0) ? 1 : 0;
        atomicAdd(&zeros, z);
        __syncthreads();
        if (threadIdx.x == 0) g_is64 = (zeros > 128) ? 1 : 0;
    }
}

__device__ __forceinline__ int load_idx(const int* ei32, size_t pos) {
    if (g_is64) return (int)((const long long*)ei32)[pos];
    return ei32[pos];
}

// ---------------- bucketed fill: one pass, 2 edges/thread (R8-proven) -----
__global__ void fill_k(const int* __restrict__ ei32, int E) {
    int e0 = (blockIdx.x * blockDim.x + threadIdx.x) * 2;
    if (e0 >= E) return;
    int r0, r1, c0, c1;
    if (e0 + 2 <= E) {
        if (g_is64) {
            const long long* p = (const long long*)ei32;
            longlong2 rv = ((const longlong2*)p)[e0 >> 1];
            longlong2 cv = ((const longlong2*)(p + E))[e0 >> 1];
            r0 = (int)rv.x; r1 = (int)rv.y;
            c0 = (int)cv.x; c1 = (int)cv.y;
        } else {
            int2 rv = ((const int2*)ei32)[e0 >> 1];
            int2 cv = ((const int2*)(ei32 + E))[e0 >> 1];
            r0 = rv.x; r1 = rv.y;
            c0 = cv.x; c1 = cv.y;
        }
        int p0 = atomicAdd(&g_cnt[c0], 1);
        int p1 = atomicAdd(&g_cnt[c1], 1);
        g_src[(size_t)c0 * BKT + p0] = r0;
        g_src[(size_t)c1 * BKT + p1] = r1;
    } else {
        int rr = load_idx(ei32, (size_t)e0);
        int cc = load_idx(ei32, (size_t)E + e0);
        int p = atomicAdd(&g_cnt[cc], 1);
        g_src[(size_t)cc * BKT + p] = rr;
    }
}

// ---------------- fused linear + pre-scale: g_feat = (x@W)*dinv -----------
// (R8-proven plain-FFMA version; dinv inline from final g_cnt.)
__global__ __launch_bounds__(128) void gemm_k(
    const float* __restrict__ x, const float* __restrict__ W, int n)
{
    __shared__ float4 Ws[INC * (OUTC / 4)];  // [k][o4], 32 KB
    const float4* W4 = (const float4*)W;
    for (int i = threadIdx.x; i < INC * (OUTC / 4); i += 128) Ws[i] = W4[i];
    __syncthreads();

    int row = blockIdx.x * 128 + threadIdx.x;
    if (row >= n) return;

    float acc[OUTC];
#pragma unroll
    for (int o = 0; o < OUTC; o++) acc[o] = 0.f;

    const float4* xr = (const float4*)(x + (size_t)row * INC);
#pragma unroll 4
    for (int k4 = 0; k4 < INC / 4; k4++) {
        float4 xq = __ldg(xr + k4);
        float xv[4] = {xq.x, xq.y, xq.z, xq.w};
#pragma unroll
        for (int j = 0; j < 4; j++) {
            int k = k4 * 4 + j;
#pragma unroll
            for (int o4 = 0; o4 < OUTC / 4; o4++) {
                float4 w = Ws[k * (OUTC / 4) + o4];
                acc[o4 * 4 + 0] += xv[j] * w.x;
                acc[o4 * 4 + 1] += xv[j] * w.y;
                acc[o4 * 4 + 2] += xv[j] * w.z;
                acc[o4 * 4 + 3] += xv[j] * w.w;
            }
        }
    }

    float s = rsqrtf((float)(g_cnt[row] + 1));   // +1 self-loop
    float4* gp = (float4*)(g_feat + (size_t)row * OUTC);
#pragma unroll
    for (int o4 = 0; o4 < OUTC / 4; o4++) {
        gp[o4] = make_float4(acc[o4 * 4 + 0] * s, acc[o4 * 4 + 1] * s,
                             acc[o4 * 4 + 2] * s, acc[o4 * 4 + 3] * s);
    }
}

// ---------------- warp-per-node gather + epilogue ----------------
// Warp loads 32 src indices coalesced from its bucket, shuffles each out; all
// 32 lanes load a packed float2 (64-bit) slice per edge and accumulate with
// ONE add.rn.f32x2 (full fp32 precision, 1 instr for 2 channels).
// 4 warp-instructions per edge: SHFL, IMAD, LDG.64, ADD.f32x2.
__global__ __launch_bounds__(256) void gather_k(
    const float* __restrict__ b, float* __restrict__ out, int n)
{
    int warp = (blockIdx.x * blockDim.x + threadIdx.x) >> 5;
    if (warp >= n) return;
    int lane = threadIdx.x & 31;

    const unsigned long long* gf =
        (const unsigned long long*)g_feat;        // 32 packed float2 per node

    // two rotating packed accumulators; acc0 starts with the self-loop term
    unsigned long long acc0 = __ldg(gf + (size_t)warp * 32 + lane);
    unsigned long long acc1 = 0ULL;               // (+0.0f, +0.0f)

    int cnt = g_cnt[warp];
    const int* bucket = g_src + (size_t)warp * BKT;
    for (int base = 0; base < cnt; base += 32) {
        int rem = cnt - base;
        int idx = (lane < rem) ? bucket[base + lane] : 0;
        if (rem >= 32) {
#pragma unroll
            for (int k = 0; k < 32; k += 2) {
                int r0 = __shfl_sync(0xffffffffu, idx, k);
                int r1 = __shfl_sync(0xffffffffu, idx, k + 1);
                unsigned long long v0 = __ldg(gf + (size_t)r0 * 32 + lane);
                unsigned long long v1 = __ldg(gf + (size_t)r1 * 32 + lane);
                asm("add.rn.f32x2 %0, %0, %1;" : "+l"(acc0) : "l"(v0));
                asm("add.rn.f32x2 %0, %0, %1;" : "+l"(acc1) : "l"(v1));
            }
        } else {
            for (int k = 0; k < rem; k++) {
                int r = __shfl_sync(0xffffffffu, idx, k);
                unsigned long long v = __ldg(gf + (size_t)r * 32 + lane);
                asm("add.rn.f32x2 %0, %0, %1;" : "+l"(acc0) : "l"(v));
            }
        }
    }

    asm("add.rn.f32x2 %0, %0, %1;" : "+l"(acc0) : "l"(acc1));
    unsigned int lo, hi;
    asm("mov.b64 {%0, %1}, %2;" : "=r"(lo), "=r"(hi) : "l"(acc0));

    float  s  = rsqrtf((float)(cnt + 1));
    float2 bq = __ldg((const float2*)b + lane);
    float2 o;
    o.x = __uint_as_float(lo) * s + bq.x;
    o.y = __uint_as_float(hi) * s + bq.y;
    ((float2*)out)[(size_t)warp * 32 + lane] = o;
}

extern "C" void kernel_launch(void* const* d_in, const int* in_sizes, int n_in,
                              void* d_out, int out_size)
{
    const float* x    = (const float*)d_in[0];
    const int*   ei32 = (const int*)d_in[1];
    const float* W    = (const float*)d_in[2];
    const float* b    = (const float*)d_in[3];
    float* out = (float*)d_out;

    int n = in_sizes[0] / INC;   // 50000
    int E = in_sizes[1] / 2;     // 1600000

    zero_k<<<(n + 255) / 256, 256>>>(ei32, n);          // + dtype detect
    fill_k<<<(E / 2 + 255) / 256, 256>>>(ei32, E);      // bucketed, 2 edges/thread
    gemm_k<<<(n + 127) / 128, 128>>>(x, W, n);          // dinv from cnt
    gather_k<<<(n * 32 + 255) / 256, 256>>>(b, out, n); // f32x2 packed adds
}

// round 11
// speedup vs baseline: 1.1811x; 1.0635x over previous
#include <cuda_runtime.h>
#include <cuda_fp16.h>
#include <cstdint>

#define NN   50000
#define EE   1600000
#define INC  128
#define OUTC 64
#define BKT  96          // fixed bucket capacity per node (mean deg 32, +11 sigma)

// Scratch (allocation-free contract: __device__ globals)
__device__ int   g_cnt[NN];                         // degree / fill cursor
__device__ __align__(16) __half g_feat[(size_t)(NN + 1) * OUTC];  // +1 zero row
__device__ int   g_src[(size_t)NN * BKT];           // bucketed source ids (19.2 MB)
__device__ int   g_is64;

// ---------------- zero + dtype detect (fused) ----------------
__global__ void zero_k(const int* __restrict__ ei32, int n) {
    int i = blockIdx.x * blockDim.x + threadIdx.x;
    if (i < n) g_cnt[i] = 0;
    if (blockIdx.x == 0) {
        // dtype probe: odd 32-bit words are zero iff int64 (high halves)
        __shared__ int zeros;
        if (threadIdx.x == 0) zeros = 0;
        __syncthreads();
        int z = (ei32[2 * threadIdx.x + 1] == 0) ? 1 : 0;
        atomicAdd(&zeros, z);
        __syncthreads();
        if (threadIdx.x == 0) g_is64 = (zeros > 128) ? 1 : 0;
    }
    if (blockIdx.x == 1 && threadIdx.x < 32) {
        // zero-feature pad row (index NN): 64 halves = 32 uint32
        ((unsigned int*)(g_feat + (size_t)NN * OUTC))[threadIdx.x] = 0u;
    }
}

__device__ __forceinline__ int load_idx(const int* ei32, size_t pos) {
    if (g_is64) return (int)((const long long*)ei32)[pos];
    return ei32[pos];
}

// ---------------- bucketed fill: one pass, 2 edges/thread (R8-proven) -----
__global__ void fill_k(const int* __restrict__ ei32, int E) {
    int e0 = (blockIdx.x * blockDim.x + threadIdx.x) * 2;
    if (e0 >= E) return;
    int r0, r1, c0, c1;
    if (e0 + 2 <= E) {
        if (g_is64) {
            const long long* p = (const long long*)ei32;
            longlong2 rv = ((const longlong2*)p)[e0 >> 1];
            longlong2 cv = ((const longlong2*)(p + E))[e0 >> 1];
            r0 = (int)rv.x; r1 = (int)rv.y;
            c0 = (int)cv.x; c1 = (int)cv.y;
        } else {
            int2 rv = ((const int2*)ei32)[e0 >> 1];
            int2 cv = ((const int2*)(ei32 + E))[e0 >> 1];
            r0 = rv.x; r1 = rv.y;
            c0 = cv.x; c1 = cv.y;
        }
        int p0 = atomicAdd(&g_cnt[c0], 1);
        int p1 = atomicAdd(&g_cnt[c1], 1);
        g_src[(size_t)c0 * BKT + p0] = r0;
        g_src[(size_t)c1 * BKT + p1] = r1;
    } else {
        int rr = load_idx(ei32, (size_t)e0);
        int cc = load_idx(ei32, (size_t)E + e0);
        int p = atomicAdd(&g_cnt[cc], 1);
        g_src[(size_t)cc * BKT + p] = rr;
    }
}

// ---------------- fused linear + pre-scale: g_feat = fp16((x@W)*dinv) ------
// (R8-proven plain-FFMA version; dinv inline from final g_cnt.)
__global__ __launch_bounds__(128) void gemm_k(
    const float* __restrict__ x, const float* __restrict__ W, int n)
{
    __shared__ float4 Ws[INC * (OUTC / 4)];  // [k][o4], 32 KB
    const float4* W4 = (const float4*)W;
    for (int i = threadIdx.x; i < INC * (OUTC / 4); i += 128) Ws[i] = W4[i];
    __syncthreads();

    int row = blockIdx.x * 128 + threadIdx.x;
    if (row >= n) return;

    float acc[OUTC];
#pragma unroll
    for (int o = 0; o < OUTC; o++) acc[o] = 0.f;

    const float4* xr = (const float4*)(x + (size_t)row * INC);
#pragma unroll 4
    for (int k4 = 0; k4 < INC / 4; k4++) {
        float4 xq = __ldg(xr + k4);
        float xv[4] = {xq.x, xq.y, xq.z, xq.w};
#pragma unroll
        for (int j = 0; j < 4; j++) {
            int k = k4 * 4 + j;
#pragma unroll
            for (int o4 = 0; o4 < OUTC / 4; o4++) {
                float4 w = Ws[k * (OUTC / 4) + o4];
                acc[o4 * 4 + 0] += xv[j] * w.x;
                acc[o4 * 4 + 1] += xv[j] * w.y;
                acc[o4 * 4 + 2] += xv[j] * w.z;
                acc[o4 * 4 + 3] += xv[j] * w.w;
            }
        }
    }

    float s = rsqrtf((float)(g_cnt[row] + 1));   // +1 self-loop
    __half2* gp = (__half2*)(g_feat + (size_t)row * OUTC);  // 32 half2
#pragma unroll
    for (int o2 = 0; o2 < OUTC / 2; o2++) {
        gp[o2] = __floats2half2_rn(acc[o2 * 2] * s, acc[o2 * 2 + 1] * s);
    }
}

// ---------------- warp-per-node gather + epilogue ----------------
// Warp loads 32 src indices coalesced; partial groups are PADDED with the
// zero row (index NN) whose single 128B line stays L1-resident -> no tail
// loop, no dynamic accumulator indexing. 8 NAMED half2 accumulators (cannot
// be demoted to local). Per edge: SHFL + IMAD + LDG.32 + HADD2 = 4 instr,
// 128B/edge of L2 traffic. Final combine + dinv scale + bias in fp32.
__global__ __launch_bounds__(256) void gather_k(
    const float* __restrict__ b, float* __restrict__ out, int n)
{
    int warp = (blockIdx.x * blockDim.x + threadIdx.x) >> 5;
    if (warp >= n) return;
    int lane = threadIdx.x & 31;

    const __half2* gf = (const __half2*)g_feat;   // 32 half2 per node
    float2 self = __half22float2(gf[(size_t)warp * 32 + lane]);  // self-loop

    __half2 z = __float2half2_rn(0.f);
    __half2 a0 = z, a1 = z, a2 = z, a3 = z, a4 = z, a5 = z, a6 = z, a7 = z;

    int cnt = g_cnt[warp];
    const int* bucket = g_src + (size_t)warp * BKT;

#define GSTEP(K, ACC) { int _r = __shfl_sync(0xffffffffu, idx, (K)); \
                        ACC = __hadd2(ACC, __ldg(gf + (size_t)_r * 32 + lane)); }

    for (int base = 0; base < cnt; base += 32) {
        int rem = cnt - base;
        int idx = (lane < rem) ? bucket[base + lane] : NN;   // pad -> zero row
        // group 0: edges k=0..15 (always at least 1 real edge here)
        GSTEP(0,  a0) GSTEP(1,  a1) GSTEP(2,  a2) GSTEP(3,  a3)
        GSTEP(4,  a4) GSTEP(5,  a5) GSTEP(6,  a6) GSTEP(7,  a7)
        GSTEP(8,  a0) GSTEP(9,  a1) GSTEP(10, a2) GSTEP(11, a3)
        GSTEP(12, a4) GSTEP(13, a5) GSTEP(14, a6) GSTEP(15, a7)
        if (rem > 16) {
            GSTEP(16, a0) GSTEP(17, a1) GSTEP(18, a2) GSTEP(19, a3)
            GSTEP(20, a4) GSTEP(21, a5) GSTEP(22, a6) GSTEP(23, a7)
            GSTEP(24, a0) GSTEP(25, a1) GSTEP(26, a2) GSTEP(27, a3)
            GSTEP(28, a4) GSTEP(29, a5) GSTEP(30, a6) GSTEP(31, a7)
        }
    }
#undef GSTEP

    // combine in fp32
    float2 acc = self;
    {
        float2 v;
        v = __half22float2(a0); acc.x += v.x; acc.y += v.y;
        v = __half22float2(a1); acc.x += v.x; acc.y += v.y;
        v = __half22float2(a2); acc.x += v.x; acc.y += v.y;
        v = __half22float2(a3); acc.x += v.x; acc.y += v.y;
        v = __half22float2(a4); acc.x += v.x; acc.y += v.y;
        v = __half22float2(a5); acc.x += v.x; acc.y += v.y;
        v = __half22float2(a6); acc.x += v.x; acc.y += v.y;
        v = __half22float2(a7); acc.x += v.x; acc.y += v.y;
    }

    float  s  = rsqrtf((float)(cnt + 1));
    float2 bq = __ldg((const float2*)b + lane);
    float2 o;
    o.x = acc.x * s + bq.x;
    o.y = acc.y * s + bq.y;
    ((float2*)out)[(size_t)warp * 32 + lane] = o;
}

extern "C" void kernel_launch(void* const* d_in, const int* in_sizes, int n_in,
                              void* d_out, int out_size)
{
    const float* x    = (const float*)d_in[0];
    const int*   ei32 = (const int*)d_in[1];
    const float* W    = (const float*)d_in[2];
    const float* b    = (const float*)d_in[3];
    float* out = (float*)d_out;

    int n = in_sizes[0] / INC;   // 50000
    int E = in_sizes[1] / 2;     // 1600000

    zero_k<<<(n + 255) / 256, 256>>>(ei32, n);          // + dtype detect + zero row
    fill_k<<<(E / 2 + 255) / 256, 256>>>(ei32, E);      // bucketed, 2 edges/thread
    gemm_k<<<(n + 127) / 128, 128>>>(x, W, n);          // dinv from cnt
    gather_k<<<(n * 32 + 255) / 256, 256>>>(b, out, n); // fp16 HADD2, no tail
}